// round 2
// baseline (speedup 1.0000x reference)
#include <cuda_runtime.h>

// Shapes (fixed by the problem)
#define Bn   8
#define NIN  4096
#define DIN  128
#define KOUT 256

#define ADJ_PER_B  (NIN * NIN)          // 16,777,216
#define ADJ_TOTAL  (Bn * ADJ_PER_B)     // 134,217,728 floats (512 MB)

// Grid geometry for the big reduction
#define ADJ_BLOCKS   2048               // 256 blocks per batch, 65536 elems each
#define ADJ_PER_BATCH (ADJ_BLOCKS / Bn) // 256
#define NODE_BLOCKS  128                // 16 per batch, 256 n-rows each
#define NODE_PER_BATCH (NODE_BLOCKS / Bn) // 16
#define RTHREADS     256

// Scratch partials — every slot is fully overwritten each launch, so no
// zeroing kernel and no atomics are needed (deterministic).
__device__ float g_adj_part[ADJ_BLOCKS];
__device__ float g_node_part[NODE_BLOCKS * DIN];

// ---------------------------------------------------------------------------
// Kernel 1: blocks [0, ADJ_BLOCKS)            -> per-block partial sum of adj
//           blocks [ADJ_BLOCKS, +NODE_BLOCKS) -> per-block partial colsum of node
// C == ones exactly (softmax over a size-1 axis), so these two reductions are
// the entire data-dependent work of the layer.
// ---------------------------------------------------------------------------
__global__ void mp_reduce_kernel(const float* __restrict__ adj,
                                 const float* __restrict__ node) {
    const int bid = blockIdx.x;

    if (bid < ADJ_BLOCKS) {
        // ---- adj partial sum: contiguous 65536-element chunk per block ----
        const int f4_per_block = (ADJ_TOTAL / ADJ_BLOCKS) / 4;   // 16384 float4
        const float4* __restrict__ base =
            reinterpret_cast<const float4*>(adj) + (size_t)bid * f4_per_block;

        // Two independent accumulators -> more loads in flight.
        float acc0 = 0.0f, acc1 = 0.0f;
        #pragma unroll 4
        for (int i = threadIdx.x; i < f4_per_block; i += 2 * RTHREADS) {
            float4 v0 = base[i];
            float4 v1 = base[i + RTHREADS];
            acc0 += (v0.x + v0.y) + (v0.z + v0.w);
            acc1 += (v1.x + v1.y) + (v1.z + v1.w);
        }
        float acc = acc0 + acc1;

        __shared__ float sf[RTHREADS];
        sf[threadIdx.x] = acc;
        __syncthreads();
        for (int s = RTHREADS / 2; s > 0; s >>= 1) {
            if (threadIdx.x < s) sf[threadIdx.x] += sf[threadIdx.x + s];
            __syncthreads();
        }
        if (threadIdx.x == 0) g_adj_part[bid] = sf[0];
    } else {
        // ---- node_set partial column sum: 256 n-rows per block ----
        const int nb   = bid - ADJ_BLOCKS;                       // 0..127
        const int b    = nb / NODE_PER_BATCH;
        const int sub  = nb % NODE_PER_BATCH;
        const int rows = NIN / NODE_PER_BATCH;                   // 256
        const int row0 = sub * rows;
        const float* __restrict__ base = node + ((size_t)b * NIN + row0) * DIN;

        const int d      = threadIdx.x & (DIN - 1);
        const int stripe = threadIdx.x >> 7;                     // 0 or 1

        float acc = 0.0f;
        #pragma unroll 4
        for (int r = stripe * 128; r < stripe * 128 + 128; r++)
            acc += base[(size_t)r * DIN + d];

        __shared__ float sf[DIN];
        if (stripe == 0) sf[d] = acc;
        __syncthreads();
        if (stripe == 1) g_node_part[nb * DIN + d] = acc + sf[d];
    }
}

// ---------------------------------------------------------------------------
// Kernel 2: finalize.
//   - reduce the partials (double for the 256 adj partials)
//   - new_node_set[b,k,:] = lrelu(colsum(node_set[b]) @ lin_w + lin_b) (all k)
//   - new_adj[b,k,j]      = total_sum(adj[b])                          (all k,j)
// Output layout: [new_node_set (8,256,128) | new_adj (8,256,256)] fp32.
// ---------------------------------------------------------------------------
#define FIN_SUB 16    // sub-blocks per batch (write-bandwidth spread)

__global__ void mp_finalize_kernel(const float* __restrict__ lin_w,
                                   const float* __restrict__ lin_b,
                                   float* __restrict__ out) {
    const int b   = blockIdx.x / FIN_SUB;
    const int sub = blockIdx.x % FIN_SUB;
    const int t   = threadIdx.x;

    __shared__ double sd[RTHREADS];
    __shared__ float  c[DIN];   // colsum of node_set[b]
    __shared__ float  r[DIN];   // lrelu(colsum @ lin_w + lin_b)

    // ---- reduce adj partials for this batch (256 values, L2-hot) ----
    sd[t] = (double)g_adj_part[b * ADJ_PER_BATCH + t];
    __syncthreads();
    for (int s = RTHREADS / 2; s > 0; s >>= 1) {
        if (t < s) sd[t] += sd[t + s];
        __syncthreads();
    }
    const float aval = (float)sd[0];
    __syncthreads();

    // ---- reduce node partials -> colsum ----
    if (t < DIN) {
        float s = 0.0f;
        #pragma unroll
        for (int p = 0; p < NODE_PER_BATCH; p++)
            s += g_node_part[(b * NODE_PER_BATCH + p) * DIN + t];
        c[t] = s;
    }
    __syncthreads();

    // ---- GEMV + leaky ReLU ----
    if (t < DIN) {
        float acc = lin_b[t];
        #pragma unroll 8
        for (int d = 0; d < DIN; d++)
            acc = fmaf(c[d], lin_w[d * DIN + t], acc);   // coalesced over t
        r[t] = (acc >= 0.0f) ? acc : 0.01f * acc;
    }
    __syncthreads();

    // --- node region: batch b spans KOUT*DIN = 32768 floats = 8192 float4 ---
    {
        float4* __restrict__ node_out =
            reinterpret_cast<float4*>(out) + (size_t)b * (KOUT * DIN / 4);
        const float4* __restrict__ r4 = reinterpret_cast<const float4*>(r);
        const int f4_total = KOUT * DIN / 4;          // 8192
        const int per      = f4_total / FIN_SUB;      // 512
        for (int i = t; i < per; i += blockDim.x) {
            int idx = sub * per + i;
            node_out[idx] = r4[idx & (DIN / 4 - 1)];  // row of 32 float4, repeated
        }
    }

    // --- adj region: batch b spans KOUT*KOUT = 65536 floats = 16384 float4 ---
    {
        float4* __restrict__ adj_out =
            reinterpret_cast<float4*>(out + (size_t)Bn * KOUT * DIN) +
            (size_t)b * (KOUT * KOUT / 4);
        const float4 av4 = make_float4(aval, aval, aval, aval);
        const int per = (KOUT * KOUT / 4) / FIN_SUB;  // 1024
        float4* __restrict__ base = adj_out + (size_t)sub * per;
        for (int i = t; i < per; i += blockDim.x)
            base[i] = av4;
    }
}

// ---------------------------------------------------------------------------
// Launch. Inputs (metadata order): node_set, adj, centroids, conv_w, conv_b,
// lin_w, lin_b. centroids/conv_* are mathematically dead (softmax over a
// size-1 axis makes C identically 1), so they are never read.
// ---------------------------------------------------------------------------
extern "C" void kernel_launch(void* const* d_in, const int* in_sizes, int n_in,
                              void* d_out, int out_size) {
    const float* node  = (const float*)d_in[0];
    const float* adj   = (const float*)d_in[1];
    const float* lin_w = (const float*)d_in[5];
    const float* lin_b = (const float*)d_in[6];
    float* out = (float*)d_out;

    mp_reduce_kernel<<<ADJ_BLOCKS + NODE_BLOCKS, RTHREADS>>>(adj, node);
    mp_finalize_kernel<<<Bn * FIN_SUB, RTHREADS>>>(lin_w, lin_b, out);
}